// round 6
// baseline (speedup 1.0000x reference)
#include <cuda_runtime.h>
#include <cuda_bf16.h>
#include <math.h>
#include <stdint.h>

// Problem shape (fixed by the dataset)
#define BB 8
#define SS 2048
#define DD 1024

// Pre-split bf16 operand arrays (device globals — allocation-guard-safe)
__device__ __nv_bfloat16 g_xhi[(size_t)BB * SS * DD];
__device__ __nv_bfloat16 g_xlo[(size_t)BB * SS * DD];
__device__ __nv_bfloat16 g_xthi[(size_t)BB * SS * DD];
__device__ __nv_bfloat16 g_xtlo[(size_t)BB * SS * DD];
__device__ __nv_bfloat16 g_whi[(size_t)DD * DD];
__device__ __nv_bfloat16 g_wlo[(size_t)DD * DD];
__device__ __nv_bfloat16 g_phi[(size_t)BB * SS * DD];
__device__ __nv_bfloat16 g_plo[(size_t)BB * SS * DD];
__device__ __nv_bfloat16 g_ahi[(size_t)BB * SS * SS];
__device__ __nv_bfloat16 g_alo[(size_t)BB * SS * SS];

// ============================================================
// Tensor-core NT GEMM via mma.sync bf16 (legacy path; tcgen05 not
// available under this toolchain's plain sm_103 PTX target).
// fp32 emulated via PRE-SPLIT bf16 hi/lo operands, 3 products (hh, hl, lh).
// R6: hot loop is cp.async(bf16)->ldsm->mma only; all splitting moved to
// one-time prep kernels / epilogues / softmax.
// CTA tile 128x128, K-chunk 64, double-buffered smem (4 tiles x 16KB x 2).
// ============================================================

#define TILE_B  16384
#define BUF_B   65536
#define GEMM_SMEM (2 * BUF_B)   // 128 KB

__device__ __forceinline__ uint32_t smem_u32(const void* p) {
    uint32_t a;
    asm("{ .reg .u64 t; cvta.to.shared.u64 t, %1; cvt.u32.u64 %0, t; }" : "=r"(a) : "l"(p));
    return a;
}
__device__ __forceinline__ uint32_t sw128(uint32_t off) {
    return off ^ ((off >> 3) & 0x70);
}
__device__ __forceinline__ void ldsm_x4(uint32_t& r0, uint32_t& r1, uint32_t& r2, uint32_t& r3,
                                        uint32_t addr) {
    asm volatile("ldmatrix.sync.aligned.m8n8.x4.shared.b16 {%0,%1,%2,%3}, [%4];"
                 : "=r"(r0), "=r"(r1), "=r"(r2), "=r"(r3) : "r"(addr));
}
__device__ __forceinline__ void mma16816(float* d, const uint32_t* a, const uint32_t* b) {
    asm volatile(
        "mma.sync.aligned.m16n8k16.row.col.f32.bf16.bf16.f32 "
        "{%0,%1,%2,%3}, {%4,%5,%6,%7}, {%8,%9}, {%0,%1,%2,%3};"
        : "+f"(d[0]), "+f"(d[1]), "+f"(d[2]), "+f"(d[3])
        : "r"(a[0]), "r"(a[1]), "r"(a[2]), "r"(a[3]), "r"(b[0]), "r"(b[1]));
}

#define CP_ASYNC16(dst, src) \
    asm volatile("cp.async.cg.shared.global [%0], [%1], 16;" :: "r"(dst), "l"(src) : "memory")
#define CP_COMMIT()  asm volatile("cp.async.commit_group;" ::: "memory")
#define CP_WAIT1()   asm volatile("cp.async.wait_group 1;" ::: "memory")

// Split one float4 into two bf16x4 (hi, lo-residual) packed as 2x uint32
__device__ __forceinline__ void split2(const float4& v, uint2& hi, uint2& lo) {
    __nv_bfloat162 h0 = __floats2bfloat162_rn(v.x, v.y);
    __nv_bfloat162 h1 = __floats2bfloat162_rn(v.z, v.w);
    float r0 = v.x - __bfloat162float(__low2bfloat16(h0));
    float r1 = v.y - __bfloat162float(__high2bfloat16(h0));
    float r2 = v.z - __bfloat162float(__low2bfloat16(h1));
    float r3 = v.w - __bfloat162float(__high2bfloat16(h1));
    __nv_bfloat162 l0 = __floats2bfloat162_rn(r0, r1);
    __nv_bfloat162 l1 = __floats2bfloat162_rn(r2, r3);
    hi.x = *reinterpret_cast<uint32_t*>(&h0);
    hi.y = *reinterpret_cast<uint32_t*>(&h1);
    lo.x = *reinterpret_cast<uint32_t*>(&l0);
    lo.y = *reinterpret_cast<uint32_t*>(&l1);
}

// A_hi/A_lo: [M,K] bf16 row-major; B_hi/B_lo: [N,K] bf16 row-major.
// If Chi != null: epilogue adds bias and writes split bf16 pair (GEMM1).
// Else: writes fp32 C.
__global__ __launch_bounds__(512, 1) void gemm_nt_mma(
    const __nv_bfloat16* __restrict__ Ahi, const __nv_bfloat16* __restrict__ Alo,
    const __nv_bfloat16* __restrict__ Bhi, const __nv_bfloat16* __restrict__ Blo,
    float* __restrict__ C, __nv_bfloat16* __restrict__ Chi, __nv_bfloat16* __restrict__ Clo,
    const float* __restrict__ bias,
    int M, int N, int K,
    long long strA, long long strB, long long strC)
{
    extern __shared__ __align__(1024) char smem[];
    const uint32_t sb = smem_u32(smem);
    const int tid = threadIdx.x, wid = tid >> 5, lane = tid & 31;
    const int row0 = blockIdx.y * 128, col0 = blockIdx.x * 128;

    Ahi += (size_t)blockIdx.z * strA;  Alo += (size_t)blockIdx.z * strA;
    Bhi += (size_t)blockIdx.z * strB;  Blo += (size_t)blockIdx.z * strB;

    // 4m x 4n warp grid, 32x32 warp tiles
    const int wm = wid & 3, wn = wid >> 2;
    const int m0w = wm * 32, n0w = wn * 32;

    // cp.async loader: tile = tid>>7 (0:Ahi 1:Alo 2:Bhi 3:Blo), one row each
    const int ltile = tid >> 7;
    const int lrow  = tid & 127;
    const __nv_bfloat16* gbase;
    if      (ltile == 0) gbase = Ahi + (size_t)(row0 + lrow) * K;
    else if (ltile == 1) gbase = Alo + (size_t)(row0 + lrow) * K;
    else if (ltile == 2) gbase = Bhi + (size_t)(col0 + lrow) * K;
    else                 gbase = Blo + (size_t)(col0 + lrow) * K;

    // ldmatrix lane addressing
    const uint32_t a_lrow = (uint32_t)(lane & 15);
    const uint32_t a_lc8  = (uint32_t)(lane >> 4) * 8;
    const uint32_t b_lrow = (uint32_t)((lane & 7) + ((lane >> 4) & 1) * 8);
    const uint32_t b_lk8  = (uint32_t)((lane >> 3) & 1) * 8;

    float acc[2][4][4];
#pragma unroll
    for (int i = 0; i < 2; i++)
#pragma unroll
        for (int j = 0; j < 4; j++)
#pragma unroll
            for (int q = 0; q < 4; q++) acc[i][j][q] = 0.f;

    const int NCH = K >> 6;

    auto issue = [&](int ch) {
        if (ch < NCH) {
            const __nv_bfloat16* src = gbase + (ch << 6);
            uint32_t dbase = sb + (uint32_t)((ch & 1) * BUF_B + ltile * TILE_B);
            unsigned long long gp =
                (unsigned long long)__cvta_generic_to_global((const void*)src);
#pragma unroll
            for (int seg = 0; seg < 8; seg++) {
                uint32_t off = (uint32_t)(lrow * 128 + seg * 16);
                CP_ASYNC16(dbase + sw128(off), gp + seg * 16);
            }
        }
        CP_COMMIT();
    };

    auto mma_ks = [&](uint32_t base, int ks) {
        uint32_t aF[2][2][4], bF[2][4][2];
#pragma unroll
        for (int lv = 0; lv < 2; lv++) {
            uint32_t tb = base + lv * TILE_B;
#pragma unroll
            for (int mf = 0; mf < 2; mf++) {
                uint32_t off = (uint32_t)((m0w + mf * 16 + a_lrow) * 128
                                          + (ks * 16 + a_lc8) * 2);
                ldsm_x4(aF[lv][mf][0], aF[lv][mf][1], aF[lv][mf][2], aF[lv][mf][3],
                        sb + tb + sw128(off));
            }
        }
#pragma unroll
        for (int lv = 0; lv < 2; lv++) {
            uint32_t tb = base + (2 + lv) * TILE_B;
#pragma unroll
            for (int nfp = 0; nfp < 2; nfp++) {
                uint32_t off = (uint32_t)((n0w + nfp * 16 + b_lrow) * 128
                                          + (ks * 16 + b_lk8) * 2);
                uint32_t r0, r1, r2, r3;
                ldsm_x4(r0, r1, r2, r3, sb + tb + sw128(off));
                bF[lv][nfp * 2][0] = r0;      bF[lv][nfp * 2][1] = r1;
                bF[lv][nfp * 2 + 1][0] = r2;  bF[lv][nfp * 2 + 1][1] = r3;
            }
        }
#pragma unroll
        for (int mf = 0; mf < 2; mf++)
#pragma unroll
            for (int nf = 0; nf < 4; nf++) mma16816(acc[mf][nf], aF[0][mf], bF[0][nf]);
#pragma unroll
        for (int mf = 0; mf < 2; mf++)
#pragma unroll
            for (int nf = 0; nf < 4; nf++) mma16816(acc[mf][nf], aF[0][mf], bF[1][nf]);
#pragma unroll
        for (int mf = 0; mf < 2; mf++)
#pragma unroll
            for (int nf = 0; nf < 4; nf++) mma16816(acc[mf][nf], aF[1][mf], bF[0][nf]);
    };

    // prologue: stage chunks 0 and 1
    issue(0);
    issue(1);

    for (int ch = 0; ch < NCH; ch++) {
        const uint32_t cur = (uint32_t)((ch & 1) * BUF_B);
        CP_WAIT1();            // chunk ch resident
        __syncthreads();
        mma_ks(cur, 0);
        mma_ks(cur, 1);
        mma_ks(cur, 2);
        mma_ks(cur, 3);
        __syncthreads();       // all reads of 'cur' done before refill
        issue(ch + 2);
    }

    // ---- epilogue: stage accums -> smem -> coalesced writes ----
    float* eps = reinterpret_cast<float*>(smem);   // [128][132]
    const int g = lane >> 2, c = lane & 3;
#pragma unroll
    for (int mf = 0; mf < 2; mf++)
#pragma unroll
        for (int nf = 0; nf < 4; nf++) {
            int r  = m0w + mf * 16 + g;
            int cc = n0w + nf * 8 + 2 * c;
            *reinterpret_cast<float2*>(&eps[r * 132 + cc]) =
                make_float2(acc[mf][nf][0], acc[mf][nf][1]);
            *reinterpret_cast<float2*>(&eps[(r + 8) * 132 + cc]) =
                make_float2(acc[mf][nf][2], acc[mf][nf][3]);
        }
    __syncthreads();

    if (Chi) {
        // GEMM1: += bias, split, write bf16 pair
        __nv_bfloat16* ph = Chi + (size_t)blockIdx.z * strC;
        __nv_bfloat16* pl = Clo + (size_t)blockIdx.z * strC;
#pragma unroll
        for (int it = 0; it < 8; it++) {
            int idx = tid + it * 512;
            int row = idx >> 5;
            int c4  = (idx & 31) << 2;
            float4 v = *reinterpret_cast<float4*>(&eps[row * 132 + c4]);
            float4 bz = *reinterpret_cast<const float4*>(&bias[col0 + c4]);
            v.x += bz.x; v.y += bz.y; v.z += bz.z; v.w += bz.w;
            uint2 hi, lo;
            split2(v, hi, lo);
            size_t o = (size_t)(row0 + row) * N + col0 + c4;
            *reinterpret_cast<uint2*>(&ph[o]) = hi;
            *reinterpret_cast<uint2*>(&pl[o]) = lo;
        }
    } else {
        float* Cb = C + (size_t)blockIdx.z * strC;
#pragma unroll
        for (int it = 0; it < 8; it++) {
            int idx = tid + it * 512;
            int row = idx >> 5;
            int c4  = (idx & 31) << 2;
            float4 v = *reinterpret_cast<float4*>(&eps[row * 132 + c4]);
            *reinterpret_cast<float4*>(&Cb[(size_t)(row0 + row) * N + col0 + c4]) = v;
        }
    }
}

// ============================================================
// prep_x: X -> X_hi/X_lo (same layout) + XT_hi/XT_lo (transposed)
// ============================================================
__global__ __launch_bounds__(256) void prep_x(
    const float* __restrict__ X,
    __nv_bfloat16* __restrict__ Xhi, __nv_bfloat16* __restrict__ Xlo,
    __nv_bfloat16* __restrict__ XThi, __nv_bfloat16* __restrict__ XTlo)
{
    __shared__ float t[32][33];
    const int b = blockIdx.z;
    const int s0 = blockIdx.x * 32, d0 = blockIdx.y * 32;
    const size_t bo = (size_t)b * SS * DD;
    const int tx = threadIdx.x, ty = threadIdx.y;
#pragma unroll
    for (int j = 0; j < 4; j++) {
        int s = s0 + ty + 8 * j;
        float v = X[bo + (size_t)s * DD + d0 + tx];
        t[ty + 8 * j][tx] = v;
        __nv_bfloat16 h = __float2bfloat16(v);
        Xhi[bo + (size_t)s * DD + d0 + tx] = h;
        Xlo[bo + (size_t)s * DD + d0 + tx] = __float2bfloat16(v - __bfloat162float(h));
    }
    __syncthreads();
#pragma unroll
    for (int j = 0; j < 4; j++) {
        int d = d0 + ty + 8 * j;
        float v = t[tx][ty + 8 * j];
        __nv_bfloat16 h = __float2bfloat16(v);
        XThi[bo + (size_t)d * SS + s0 + tx] = h;
        XTlo[bo + (size_t)d * SS + s0 + tx] = __float2bfloat16(v - __bfloat162float(h));
    }
}

// ============================================================
// split_w: W -> W_hi/W_lo
// ============================================================
__global__ __launch_bounds__(256) void split_w(
    const float* __restrict__ W,
    __nv_bfloat16* __restrict__ Whi, __nv_bfloat16* __restrict__ Wlo)
{
    int idx = blockIdx.x * 256 + threadIdx.x;
    float4 v = reinterpret_cast<const float4*>(W)[idx];
    uint2 hi, lo;
    split2(v, hi, lo);
    reinterpret_cast<uint2*>(Whi)[idx] = hi;
    reinterpret_cast<uint2*>(Wlo)[idx] = lo;
}

// ============================================================
// In-place row softmax (rows of length SS = 2048) + split bf16 out
// ============================================================
__device__ __forceinline__ float warp_max(float v) {
#pragma unroll
    for (int o = 16; o > 0; o >>= 1) v = fmaxf(v, __shfl_xor_sync(0xFFFFFFFFu, v, o));
    return v;
}
__device__ __forceinline__ float warp_sum(float v) {
#pragma unroll
    for (int o = 16; o > 0; o >>= 1) v += __shfl_xor_sync(0xFFFFFFFFu, v, o);
    return v;
}

__global__ __launch_bounds__(256) void softmax_rows(
    float* __restrict__ attn,
    __nv_bfloat16* __restrict__ Ahi, __nv_bfloat16* __restrict__ Alo)
{
    __shared__ float red[8];
    const size_t ro = (size_t)blockIdx.x * SS;
    float* row = attn + ro;
    const int tid = threadIdx.x, lane = tid & 31, wid = tid >> 5;

    float4 v[2];
    v[0] = *reinterpret_cast<const float4*>(&row[tid * 4]);
    v[1] = *reinterpret_cast<const float4*>(&row[(tid + 256) * 4]);

    float mx = -INFINITY;
#pragma unroll
    for (int i = 0; i < 2; i++)
        mx = fmaxf(mx, fmaxf(fmaxf(v[i].x, v[i].y), fmaxf(v[i].z, v[i].w)));
    mx = warp_max(mx);
    if (lane == 0) red[wid] = mx;
    __syncthreads();
    if (wid == 0) {
        float t = (lane < 8) ? red[lane] : -INFINITY;
        t = warp_max(t);
        if (lane == 0) red[0] = t;
    }
    __syncthreads();
    mx = red[0];
    __syncthreads();

    float s = 0.f;
#pragma unroll
    for (int i = 0; i < 2; i++) {
        v[i].x = expf(v[i].x - mx); s += v[i].x;
        v[i].y = expf(v[i].y - mx); s += v[i].y;
        v[i].z = expf(v[i].z - mx); s += v[i].z;
        v[i].w = expf(v[i].w - mx); s += v[i].w;
    }
    s = warp_sum(s);
    if (lane == 0) red[wid] = s;
    __syncthreads();
    if (wid == 0) {
        float t = (lane < 8) ? red[lane] : 0.0f;
        t = warp_sum(t);
        if (lane == 0) red[0] = t;
    }
    __syncthreads();
    float inv = 1.0f / red[0];

#pragma unroll
    for (int i = 0; i < 2; i++) { v[i].x *= inv; v[i].y *= inv; v[i].z *= inv; v[i].w *= inv; }
    *reinterpret_cast<float4*>(&row[tid * 4])         = v[0];
    *reinterpret_cast<float4*>(&row[(tid + 256) * 4]) = v[1];

    // split bf16 pair for GEMM3
    uint2 hi, lo;
    split2(v[0], hi, lo);
    *reinterpret_cast<uint2*>(&Ahi[ro + tid * 4]) = hi;
    *reinterpret_cast<uint2*>(&Alo[ro + tid * 4]) = lo;
    split2(v[1], hi, lo);
    *reinterpret_cast<uint2*>(&Ahi[ro + (tid + 256) * 4]) = hi;
    *reinterpret_cast<uint2*>(&Alo[ro + (tid + 256) * 4]) = lo;
}

// ============================================================
// kernel_launch
// ============================================================
extern "C" void kernel_launch(void* const* d_in, const int* in_sizes, int n_in,
                              void* d_out, int out_size)
{
    const float* X    = (const float*)d_in[0];
    const float* W    = (const float*)d_in[1];
    const float* bias = (const float*)d_in[2];

    float* ctx  = (float*)d_out;                           // [8,2048,1024]
    float* attn = (float*)d_out + (size_t)BB * SS * DD;    // [8,2048,2048]

    __nv_bfloat16 *xhi, *xlo, *xthi, *xtlo, *whi, *wlo, *phi, *plo, *ahi, *alo;
    cudaGetSymbolAddress((void**)&xhi,  g_xhi);
    cudaGetSymbolAddress((void**)&xlo,  g_xlo);
    cudaGetSymbolAddress((void**)&xthi, g_xthi);
    cudaGetSymbolAddress((void**)&xtlo, g_xtlo);
    cudaGetSymbolAddress((void**)&whi,  g_whi);
    cudaGetSymbolAddress((void**)&wlo,  g_wlo);
    cudaGetSymbolAddress((void**)&phi,  g_phi);
    cudaGetSymbolAddress((void**)&plo,  g_plo);
    cudaGetSymbolAddress((void**)&ahi,  g_ahi);
    cudaGetSymbolAddress((void**)&alo,  g_alo);

    cudaFuncSetAttribute(gemm_nt_mma, cudaFuncAttributeMaxDynamicSharedMemorySize, GEMM_SMEM);

    const long long sXD = (long long)SS * DD;
    const long long sAA = (long long)SS * SS;

    // Prep: split X (+ transposed copy) and W
    {
        dim3 grid(SS / 32, DD / 32, BB);
        prep_x<<<grid, dim3(32, 8)>>>(X, xhi, xlo, xthi, xtlo);
    }
    split_w<<<(DD * DD / 4) / 256, 256>>>(W, whi, wlo);

    // GEMM1: proj = X * W^T + b  -> split bf16 pair
    {
        dim3 grid(DD / 128, (BB * SS) / 128, 1);
        gemm_nt_mma<<<grid, 512, GEMM_SMEM>>>(xhi, xlo, whi, wlo,
                                              nullptr, phi, plo, bias,
                                              BB * SS, DD, DD, 0, 0, sXD * 0);
    }
    // GEMM2: attn[b] = X[b] * proj[b]^T  (fp32 out to d_out)
    {
        dim3 grid(SS / 128, SS / 128, BB);
        gemm_nt_mma<<<grid, 512, GEMM_SMEM>>>(xhi, xlo, phi, plo,
                                              attn, nullptr, nullptr, nullptr,
                                              SS, SS, DD, sXD, sXD, sAA);
    }
    // Softmax in place + split bf16 pair
    softmax_rows<<<BB * SS, 256>>>(attn, ahi, alo);
    // GEMM3: ctx[b] = attn[b] * XT[b]^T  (fp32 out)
    {
        dim3 grid(DD / 128, SS / 128, BB);
        gemm_nt_mma<<<grid, 512, GEMM_SMEM>>>(ahi, alo, xthi, xtlo,
                                              ctx, nullptr, nullptr, nullptr,
                                              SS, DD, SS, sAA, sXD, sXD);
    }
}

// round 7
// speedup vs baseline: 1.3930x; 1.3930x over previous
#include <cuda_runtime.h>
#include <cuda_bf16.h>
#include <math.h>
#include <stdint.h>

// Problem shape (fixed by the dataset)
#define BB 8
#define SS 2048
#define DD 1024

// Pre-split bf16 operand arrays (device globals — allocation-guard-safe)
__device__ __nv_bfloat16 g_xhi[(size_t)BB * SS * DD];
__device__ __nv_bfloat16 g_xlo[(size_t)BB * SS * DD];
__device__ __nv_bfloat16 g_xthi[(size_t)BB * SS * DD];
__device__ __nv_bfloat16 g_xtlo[(size_t)BB * SS * DD];
__device__ __nv_bfloat16 g_whi[(size_t)DD * DD];
__device__ __nv_bfloat16 g_wlo[(size_t)DD * DD];
__device__ __nv_bfloat16 g_phi[(size_t)BB * SS * DD];
__device__ __nv_bfloat16 g_plo[(size_t)BB * SS * DD];
__device__ __nv_bfloat16 g_ahi[(size_t)BB * SS * SS];
__device__ __nv_bfloat16 g_alo[(size_t)BB * SS * SS];

// ============================================================
// R7 GEMM: 256 threads, CTA tile 128(M) x 64(N), BK=64, 2 CTAs/SM.
// 8 warps as 4m x 2n, warp tile 32x32.
// Pre-split bf16 hi/lo operands, 3 products (hh, hl, lh).
// smem/stage: Ahi 16K | Alo 16K | Bhi 8K | Blo 8K = 48KB; x2 stages = 96KB.
// ============================================================

#define A_T   16384
#define B_T   8192
#define STAGE_B 49152
#define GEMM_SMEM (2 * STAGE_B)   // 96 KB

__device__ __forceinline__ uint32_t smem_u32(const void* p) {
    uint32_t a;
    asm("{ .reg .u64 t; cvta.to.shared.u64 t, %1; cvt.u32.u64 %0, t; }" : "=r"(a) : "l"(p));
    return a;
}
__device__ __forceinline__ uint32_t sw128(uint32_t off) {
    return off ^ ((off >> 3) & 0x70);
}
__device__ __forceinline__ void ldsm_x4(uint32_t& r0, uint32_t& r1, uint32_t& r2, uint32_t& r3,
                                        uint32_t addr) {
    asm volatile("ldmatrix.sync.aligned.m8n8.x4.shared.b16 {%0,%1,%2,%3}, [%4];"
                 : "=r"(r0), "=r"(r1), "=r"(r2), "=r"(r3) : "r"(addr));
}
__device__ __forceinline__ void mma16816(float* d, const uint32_t* a, const uint32_t* b) {
    asm volatile(
        "mma.sync.aligned.m16n8k16.row.col.f32.bf16.bf16.f32 "
        "{%0,%1,%2,%3}, {%4,%5,%6,%7}, {%8,%9}, {%0,%1,%2,%3};"
        : "+f"(d[0]), "+f"(d[1]), "+f"(d[2]), "+f"(d[3])
        : "r"(a[0]), "r"(a[1]), "r"(a[2]), "r"(a[3]), "r"(b[0]), "r"(b[1]));
}

#define CP_ASYNC16(dst, src) \
    asm volatile("cp.async.cg.shared.global [%0], [%1], 16;" :: "r"(dst), "l"(src) : "memory")
#define CP_COMMIT()  asm volatile("cp.async.commit_group;" ::: "memory")
#define CP_WAIT1()   asm volatile("cp.async.wait_group 1;" ::: "memory")

__device__ __forceinline__ void split2(const float4& v, uint2& hi, uint2& lo) {
    __nv_bfloat162 h0 = __floats2bfloat162_rn(v.x, v.y);
    __nv_bfloat162 h1 = __floats2bfloat162_rn(v.z, v.w);
    float r0 = v.x - __bfloat162float(__low2bfloat16(h0));
    float r1 = v.y - __bfloat162float(__high2bfloat16(h0));
    float r2 = v.z - __bfloat162float(__low2bfloat16(h1));
    float r3 = v.w - __bfloat162float(__high2bfloat16(h1));
    __nv_bfloat162 l0 = __floats2bfloat162_rn(r0, r1);
    __nv_bfloat162 l1 = __floats2bfloat162_rn(r2, r3);
    hi.x = *reinterpret_cast<uint32_t*>(&h0);
    hi.y = *reinterpret_cast<uint32_t*>(&h1);
    lo.x = *reinterpret_cast<uint32_t*>(&l0);
    lo.y = *reinterpret_cast<uint32_t*>(&l1);
}

__global__ __launch_bounds__(256, 2) void gemm_nt_mma(
    const __nv_bfloat16* __restrict__ Ahi, const __nv_bfloat16* __restrict__ Alo,
    const __nv_bfloat16* __restrict__ Bhi, const __nv_bfloat16* __restrict__ Blo,
    float* __restrict__ C, __nv_bfloat16* __restrict__ Chi, __nv_bfloat16* __restrict__ Clo,
    const float* __restrict__ bias,
    int M, int N, int K,
    long long strA, long long strB, long long strC)
{
    extern __shared__ __align__(1024) char smem[];
    const uint32_t sb = smem_u32(smem);
    const int tid = threadIdx.x, wid = tid >> 5, lane = tid & 31;
    const int row0 = blockIdx.y * 128, col0 = blockIdx.x * 64;

    Ahi += (size_t)blockIdx.z * strA;  Alo += (size_t)blockIdx.z * strA;
    Bhi += (size_t)blockIdx.z * strB;  Blo += (size_t)blockIdx.z * strB;

    // 4m x 2n warp grid, 32x32 warp tiles
    const int wm = wid & 3, wn = wid >> 2;
    const int m0w = wm * 32, n0w = wn * 32;

    // ---- cp.async loader indexing ----
    // A tiles: thread covers 64B of one row: row = tid>>1, 4 segs at (tid&1)*4+s
    const int la_row = tid >> 1;
    const int la_c0  = (tid & 1) * 4;
    // B tiles: thread covers 32B of one row: row = tid>>2, 2 segs at (tid&3)*2+s
    const int lb_row = tid >> 2;
    const int lb_c0  = (tid & 3) * 2;

    const __nv_bfloat16* gAhi = Ahi + (size_t)(row0 + la_row) * K + la_c0 * 8;
    const __nv_bfloat16* gAlo = Alo + (size_t)(row0 + la_row) * K + la_c0 * 8;
    const __nv_bfloat16* gBhi = Bhi + (size_t)(col0 + lb_row) * K + lb_c0 * 8;
    const __nv_bfloat16* gBlo = Blo + (size_t)(col0 + lb_row) * K + lb_c0 * 8;

    // ldmatrix lane addressing
    const uint32_t a_lrow = (uint32_t)(lane & 15);
    const uint32_t a_lc8  = (uint32_t)(lane >> 4) * 8;
    const uint32_t b_lrow = (uint32_t)((lane & 7) + ((lane >> 4) & 1) * 8);
    const uint32_t b_lk8  = (uint32_t)((lane >> 3) & 1) * 8;

    float acc[2][4][4];
#pragma unroll
    for (int i = 0; i < 2; i++)
#pragma unroll
        for (int j = 0; j < 4; j++)
#pragma unroll
            for (int q = 0; q < 4; q++) acc[i][j][q] = 0.f;

    const int NCH = K >> 6;

    auto issue = [&](int ch) {
        if (ch < NCH) {
            const uint32_t st = sb + (uint32_t)((ch & 1) * STAGE_B);
            const long long koff = (long long)(ch << 6);
            unsigned long long pah =
                (unsigned long long)__cvta_generic_to_global((const void*)(gAhi + koff));
            unsigned long long pal =
                (unsigned long long)__cvta_generic_to_global((const void*)(gAlo + koff));
            unsigned long long pbh =
                (unsigned long long)__cvta_generic_to_global((const void*)(gBhi + koff));
            unsigned long long pbl =
                (unsigned long long)__cvta_generic_to_global((const void*)(gBlo + koff));
#pragma unroll
            for (int s = 0; s < 4; s++) {
                uint32_t off = (uint32_t)(la_row * 128 + (la_c0 + s) * 16);
                uint32_t sw = sw128(off);
                CP_ASYNC16(st + sw,       pah + s * 16);
                CP_ASYNC16(st + A_T + sw, pal + s * 16);
            }
#pragma unroll
            for (int s = 0; s < 2; s++) {
                uint32_t off = (uint32_t)(lb_row * 128 + (lb_c0 + s) * 16);
                uint32_t sw = sw128(off);
                CP_ASYNC16(st + 2 * A_T + sw,       pbh + s * 16);
                CP_ASYNC16(st + 2 * A_T + B_T + sw, pbl + s * 16);
            }
        }
        CP_COMMIT();
    };

    // Interleaved phases: (ldsm A0,B0 -> 8 mma) (ldsm B1 -> 8 mma) (ldsm A1 -> 8 mma)
    auto mma_ks = [&](uint32_t base, int ks) {
        uint32_t aF0[2][4], aF1[2][4], bF0[4][2], bF1[4][2];
        // phase 1
#pragma unroll
        for (int mf = 0; mf < 2; mf++) {
            uint32_t off = (uint32_t)((m0w + mf * 16 + a_lrow) * 128 + (ks * 16 + a_lc8) * 2);
            ldsm_x4(aF0[mf][0], aF0[mf][1], aF0[mf][2], aF0[mf][3], base + sw128(off));
        }
#pragma unroll
        for (int nfp = 0; nfp < 2; nfp++) {
            uint32_t off = (uint32_t)((n0w + nfp * 16 + b_lrow) * 128 + (ks * 16 + b_lk8) * 2);
            uint32_t r0, r1, r2, r3;
            ldsm_x4(r0, r1, r2, r3, base + 2 * A_T + sw128(off));
            bF0[nfp * 2][0] = r0;      bF0[nfp * 2][1] = r1;
            bF0[nfp * 2 + 1][0] = r2;  bF0[nfp * 2 + 1][1] = r3;
        }
#pragma unroll
        for (int mf = 0; mf < 2; mf++)
#pragma unroll
            for (int nf = 0; nf < 4; nf++) mma16816(acc[mf][nf], aF0[mf], bF0[nf]);
        // phase 2: B lo
#pragma unroll
        for (int nfp = 0; nfp < 2; nfp++) {
            uint32_t off = (uint32_t)((n0w + nfp * 16 + b_lrow) * 128 + (ks * 16 + b_lk8) * 2);
            uint32_t r0, r1, r2, r3;
            ldsm_x4(r0, r1, r2, r3, base + 2 * A_T + B_T + sw128(off));
            bF1[nfp * 2][0] = r0;      bF1[nfp * 2][1] = r1;
            bF1[nfp * 2 + 1][0] = r2;  bF1[nfp * 2 + 1][1] = r3;
        }
#pragma unroll
        for (int mf = 0; mf < 2; mf++)
#pragma unroll
            for (int nf = 0; nf < 4; nf++) mma16816(acc[mf][nf], aF0[mf], bF1[nf]);
        // phase 3: A lo
#pragma unroll
        for (int mf = 0; mf < 2; mf++) {
            uint32_t off = (uint32_t)((m0w + mf * 16 + a_lrow) * 128 + (ks * 16 + a_lc8) * 2);
            ldsm_x4(aF1[mf][0], aF1[mf][1], aF1[mf][2], aF1[mf][3], base + A_T + sw128(off));
        }
#pragma unroll
        for (int mf = 0; mf < 2; mf++)
#pragma unroll
            for (int nf = 0; nf < 4; nf++) mma16816(acc[mf][nf], aF1[mf], bF0[nf]);
    };

    issue(0);
    issue(1);

    for (int ch = 0; ch < NCH; ch++) {
        const uint32_t cur = sb + (uint32_t)((ch & 1) * STAGE_B);
        CP_WAIT1();
        __syncthreads();
        mma_ks(cur, 0);
        mma_ks(cur, 1);
        mma_ks(cur, 2);
        mma_ks(cur, 3);
        __syncthreads();
        issue(ch + 2);
    }

    // ---- epilogue: stage accums -> smem [128][68] -> coalesced writes ----
    float* eps = reinterpret_cast<float*>(smem);
    const int g = lane >> 2, c = lane & 3;
#pragma unroll
    for (int mf = 0; mf < 2; mf++)
#pragma unroll
        for (int nf = 0; nf < 4; nf++) {
            int r  = m0w + mf * 16 + g;
            int cc = n0w + nf * 8 + 2 * c;
            *reinterpret_cast<float2*>(&eps[r * 68 + cc]) =
                make_float2(acc[mf][nf][0], acc[mf][nf][1]);
            *reinterpret_cast<float2*>(&eps[(r + 8) * 68 + cc]) =
                make_float2(acc[mf][nf][2], acc[mf][nf][3]);
        }
    __syncthreads();

    if (Chi) {
        __nv_bfloat16* ph = Chi + (size_t)blockIdx.z * strC;
        __nv_bfloat16* pl = Clo + (size_t)blockIdx.z * strC;
#pragma unroll
        for (int it = 0; it < 8; it++) {
            int idx = tid + it * 256;
            int row = idx >> 4;
            int c4  = (idx & 15) << 2;
            float4 v = *reinterpret_cast<float4*>(&eps[row * 68 + c4]);
            float4 bz = *reinterpret_cast<const float4*>(&bias[col0 + c4]);
            v.x += bz.x; v.y += bz.y; v.z += bz.z; v.w += bz.w;
            uint2 hi, lo;
            split2(v, hi, lo);
            size_t o = (size_t)(row0 + row) * N + col0 + c4;
            *reinterpret_cast<uint2*>(&ph[o]) = hi;
            *reinterpret_cast<uint2*>(&pl[o]) = lo;
        }
    } else {
        float* Cb = C + (size_t)blockIdx.z * strC;
#pragma unroll
        for (int it = 0; it < 8; it++) {
            int idx = tid + it * 256;
            int row = idx >> 4;
            int c4  = (idx & 15) << 2;
            float4 v = *reinterpret_cast<float4*>(&eps[row * 68 + c4]);
            *reinterpret_cast<float4*>(&Cb[(size_t)(row0 + row) * N + col0 + c4]) = v;
        }
    }
}

// ============================================================
// prep_x: X -> X_hi/X_lo + XT_hi/XT_lo
// ============================================================
__global__ __launch_bounds__(256) void prep_x(
    const float* __restrict__ X,
    __nv_bfloat16* __restrict__ Xhi, __nv_bfloat16* __restrict__ Xlo,
    __nv_bfloat16* __restrict__ XThi, __nv_bfloat16* __restrict__ XTlo)
{
    __shared__ float t[32][33];
    const int b = blockIdx.z;
    const int s0 = blockIdx.x * 32, d0 = blockIdx.y * 32;
    const size_t bo = (size_t)b * SS * DD;
    const int tx = threadIdx.x, ty = threadIdx.y;
#pragma unroll
    for (int j = 0; j < 4; j++) {
        int s = s0 + ty + 8 * j;
        float v = X[bo + (size_t)s * DD + d0 + tx];
        t[ty + 8 * j][tx] = v;
        __nv_bfloat16 h = __float2bfloat16(v);
        Xhi[bo + (size_t)s * DD + d0 + tx] = h;
        Xlo[bo + (size_t)s * DD + d0 + tx] = __float2bfloat16(v - __bfloat162float(h));
    }
    __syncthreads();
#pragma unroll
    for (int j = 0; j < 4; j++) {
        int d = d0 + ty + 8 * j;
        float v = t[tx][ty + 8 * j];
        __nv_bfloat16 h = __float2bfloat16(v);
        XThi[bo + (size_t)d * SS + s0 + tx] = h;
        XTlo[bo + (size_t)d * SS + s0 + tx] = __float2bfloat16(v - __bfloat162float(h));
    }
}

__global__ __launch_bounds__(256) void split_w(
    const float* __restrict__ W,
    __nv_bfloat16* __restrict__ Whi, __nv_bfloat16* __restrict__ Wlo)
{
    int idx = blockIdx.x * 256 + threadIdx.x;
    float4 v = reinterpret_cast<const float4*>(W)[idx];
    uint2 hi, lo;
    split2(v, hi, lo);
    reinterpret_cast<uint2*>(Whi)[idx] = hi;
    reinterpret_cast<uint2*>(Wlo)[idx] = lo;
}

// ============================================================
// In-place row softmax + split bf16 out
// ============================================================
__device__ __forceinline__ float warp_max(float v) {
#pragma unroll
    for (int o = 16; o > 0; o >>= 1) v = fmaxf(v, __shfl_xor_sync(0xFFFFFFFFu, v, o));
    return v;
}
__device__ __forceinline__ float warp_sum(float v) {
#pragma unroll
    for (int o = 16; o > 0; o >>= 1) v += __shfl_xor_sync(0xFFFFFFFFu, v, o);
    return v;
}

__global__ __launch_bounds__(256) void softmax_rows(
    float* __restrict__ attn,
    __nv_bfloat16* __restrict__ Ahi, __nv_bfloat16* __restrict__ Alo)
{
    __shared__ float red[8];
    const size_t ro = (size_t)blockIdx.x * SS;
    float* row = attn + ro;
    const int tid = threadIdx.x, lane = tid & 31, wid = tid >> 5;

    float4 v[2];
    v[0] = *reinterpret_cast<const float4*>(&row[tid * 4]);
    v[1] = *reinterpret_cast<const float4*>(&row[(tid + 256) * 4]);

    float mx = -INFINITY;
#pragma unroll
    for (int i = 0; i < 2; i++)
        mx = fmaxf(mx, fmaxf(fmaxf(v[i].x, v[i].y), fmaxf(v[i].z, v[i].w)));
    mx = warp_max(mx);
    if (lane == 0) red[wid] = mx;
    __syncthreads();
    if (wid == 0) {
        float t = (lane < 8) ? red[lane] : -INFINITY;
        t = warp_max(t);
        if (lane == 0) red[0] = t;
    }
    __syncthreads();
    mx = red[0];
    __syncthreads();

    float s = 0.f;
#pragma unroll
    for (int i = 0; i < 2; i++) {
        v[i].x = expf(v[i].x - mx); s += v[i].x;
        v[i].y = expf(v[i].y - mx); s += v[i].y;
        v[i].z = expf(v[i].z - mx); s += v[i].z;
        v[i].w = expf(v[i].w - mx); s += v[i].w;
    }
    s = warp_sum(s);
    if (lane == 0) red[wid] = s;
    __syncthreads();
    if (wid == 0) {
        float t = (lane < 8) ? red[lane] : 0.0f;
        t = warp_sum(t);
        if (lane == 0) red[0] = t;
    }
    __syncthreads();
    float inv = 1.0f / red[0];

#pragma unroll
    for (int i = 0; i < 2; i++) { v[i].x *= inv; v[i].y *= inv; v[i].z *= inv; v[i].w *= inv; }
    *reinterpret_cast<float4*>(&row[tid * 4])         = v[0];
    *reinterpret_cast<float4*>(&row[(tid + 256) * 4]) = v[1];

    uint2 hi, lo;
    split2(v[0], hi, lo);
    *reinterpret_cast<uint2*>(&Ahi[ro + tid * 4]) = hi;
    *reinterpret_cast<uint2*>(&Alo[ro + tid * 4]) = lo;
    split2(v[1], hi, lo);
    *reinterpret_cast<uint2*>(&Ahi[ro + (tid + 256) * 4]) = hi;
    *reinterpret_cast<uint2*>(&Alo[ro + (tid + 256) * 4]) = lo;
}

// ============================================================
// kernel_launch
// ============================================================
extern "C" void kernel_launch(void* const* d_in, const int* in_sizes, int n_in,
                              void* d_out, int out_size)
{
    const float* X    = (const float*)d_in[0];
    const float* W    = (const float*)d_in[1];
    const float* bias = (const float*)d_in[2];

    float* ctx  = (float*)d_out;                           // [8,2048,1024]
    float* attn = (float*)d_out + (size_t)BB * SS * DD;    // [8,2048,2048]

    __nv_bfloat16 *xhi, *xlo, *xthi, *xtlo, *whi, *wlo, *phi, *plo, *ahi, *alo;
    cudaGetSymbolAddress((void**)&xhi,  g_xhi);
    cudaGetSymbolAddress((void**)&xlo,  g_xlo);
    cudaGetSymbolAddress((void**)&xthi, g_xthi);
    cudaGetSymbolAddress((void**)&xtlo, g_xtlo);
    cudaGetSymbolAddress((void**)&whi,  g_whi);
    cudaGetSymbolAddress((void**)&wlo,  g_wlo);
    cudaGetSymbolAddress((void**)&phi,  g_phi);
    cudaGetSymbolAddress((void**)&plo,  g_plo);
    cudaGetSymbolAddress((void**)&ahi,  g_ahi);
    cudaGetSymbolAddress((void**)&alo,  g_alo);

    cudaFuncSetAttribute(gemm_nt_mma, cudaFuncAttributeMaxDynamicSharedMemorySize, GEMM_SMEM);

    const long long sXD = (long long)SS * DD;
    const long long sAA = (long long)SS * SS;

    {
        dim3 grid(SS / 32, DD / 32, BB);
        prep_x<<<grid, dim3(32, 8)>>>(X, xhi, xlo, xthi, xtlo);
    }
    split_w<<<(DD * DD / 4) / 256, 256>>>(W, whi, wlo);

    // GEMM1: proj = X * W^T + b  -> split bf16 pair
    {
        dim3 grid(DD / 64, (BB * SS) / 128, 1);
        gemm_nt_mma<<<grid, 256, GEMM_SMEM>>>(xhi, xlo, whi, wlo,
                                              nullptr, phi, plo, bias,
                                              BB * SS, DD, DD, 0, 0, 0);
    }
    // GEMM2: attn[b] = X[b] * proj[b]^T  (fp32 out)
    {
        dim3 grid(SS / 64, SS / 128, BB);
        gemm_nt_mma<<<grid, 256, GEMM_SMEM>>>(xhi, xlo, phi, plo,
                                              attn, nullptr, nullptr, nullptr,
                                              SS, SS, DD, sXD, sXD, sAA);
    }
    softmax_rows<<<BB * SS, 256>>>(attn, ahi, alo);
    // GEMM3: ctx[b] = attn[b] * XT[b]^T  (fp32 out)
    {
        dim3 grid(DD / 64, SS / 128, BB);
        gemm_nt_mma<<<grid, 256, GEMM_SMEM>>>(ahi, alo, xthi, xtlo,
                                              ctx, nullptr, nullptr, nullptr,
                                              SS, DD, SS, sAA, sXD, sXD);
    }
}

// round 8
// speedup vs baseline: 1.4715x; 1.0563x over previous
#include <cuda_runtime.h>
#include <cuda_bf16.h>
#include <math.h>
#include <stdint.h>

// Problem shape (fixed by the dataset)
#define BB 8
#define SS 2048
#define DD 1024

// Pre-split bf16 operand arrays (device globals — allocation-guard-safe)
__device__ __nv_bfloat16 g_xhi[(size_t)BB * SS * DD];
__device__ __nv_bfloat16 g_xlo[(size_t)BB * SS * DD];
__device__ __nv_bfloat16 g_xthi[(size_t)BB * SS * DD];
__device__ __nv_bfloat16 g_xtlo[(size_t)BB * SS * DD];
__device__ __nv_bfloat16 g_whi[(size_t)DD * DD];
__device__ __nv_bfloat16 g_wlo[(size_t)DD * DD];
__device__ __nv_bfloat16 g_phi[(size_t)BB * SS * DD];
__device__ __nv_bfloat16 g_plo[(size_t)BB * SS * DD];
__device__ __nv_bfloat16 g_ahi[(size_t)BB * SS * SS];
__device__ __nv_bfloat16 g_alo[(size_t)BB * SS * SS];

// ============================================================
// R8 GEMM: 256 threads, CTA tile 128(M) x 64(N), BK=32, 4-stage ring,
// ONE __syncthreads per chunk. 8 warps as 4m x 2n, warp tile 32x32.
// Pre-split bf16 hi/lo operands, 3 products (hh, hl, lh).
// Stage (24KB): Ahi 8K | Alo 8K | Bhi 4K | Blo 4K.  4 stages = 96KB.
// ============================================================

#define AH_OFF 0
#define AL_OFF 8192
#define BH_OFF 16384
#define BL_OFF 20480
#define STAGE_B 24576
#define GEMM_SMEM (4 * STAGE_B)   // 96 KB

__device__ __forceinline__ uint32_t smem_u32(const void* p) {
    uint32_t a;
    asm("{ .reg .u64 t; cvta.to.shared.u64 t, %1; cvt.u32.u64 %0, t; }" : "=r"(a) : "l"(p));
    return a;
}
// SW64 swizzle for 64-byte rows
__device__ __forceinline__ uint32_t sw64(uint32_t off) {
    return off ^ ((off >> 3) & 0x30);
}
__device__ __forceinline__ void ldsm_x4(uint32_t& r0, uint32_t& r1, uint32_t& r2, uint32_t& r3,
                                        uint32_t addr) {
    asm volatile("ldmatrix.sync.aligned.m8n8.x4.shared.b16 {%0,%1,%2,%3}, [%4];"
                 : "=r"(r0), "=r"(r1), "=r"(r2), "=r"(r3) : "r"(addr));
}
__device__ __forceinline__ void mma16816(float* d, const uint32_t* a, const uint32_t* b) {
    asm volatile(
        "mma.sync.aligned.m16n8k16.row.col.f32.bf16.bf16.f32 "
        "{%0,%1,%2,%3}, {%4,%5,%6,%7}, {%8,%9}, {%0,%1,%2,%3};"
        : "+f"(d[0]), "+f"(d[1]), "+f"(d[2]), "+f"(d[3])
        : "r"(a[0]), "r"(a[1]), "r"(a[2]), "r"(a[3]), "r"(b[0]), "r"(b[1]));
}

#define CP_ASYNC16(dst, src) \
    asm volatile("cp.async.cg.shared.global [%0], [%1], 16;" :: "r"(dst), "l"(src) : "memory")
#define CP_COMMIT()  asm volatile("cp.async.commit_group;" ::: "memory")
#define CP_WAIT2()   asm volatile("cp.async.wait_group 2;" ::: "memory")
#define CP_WAIT0()   asm volatile("cp.async.wait_group 0;" ::: "memory")

__device__ __forceinline__ void split2(const float4& v, uint2& hi, uint2& lo) {
    __nv_bfloat162 h0 = __floats2bfloat162_rn(v.x, v.y);
    __nv_bfloat162 h1 = __floats2bfloat162_rn(v.z, v.w);
    float r0 = v.x - __bfloat162float(__low2bfloat16(h0));
    float r1 = v.y - __bfloat162float(__high2bfloat16(h0));
    float r2 = v.z - __bfloat162float(__low2bfloat16(h1));
    float r3 = v.w - __bfloat162float(__high2bfloat16(h1));
    __nv_bfloat162 l0 = __floats2bfloat162_rn(r0, r1);
    __nv_bfloat162 l1 = __floats2bfloat162_rn(r2, r3);
    hi.x = *reinterpret_cast<uint32_t*>(&h0);
    hi.y = *reinterpret_cast<uint32_t*>(&h1);
    lo.x = *reinterpret_cast<uint32_t*>(&l0);
    lo.y = *reinterpret_cast<uint32_t*>(&l1);
}

__global__ __launch_bounds__(256, 2) void gemm_nt_mma(
    const __nv_bfloat16* __restrict__ Ahi, const __nv_bfloat16* __restrict__ Alo,
    const __nv_bfloat16* __restrict__ Bhi, const __nv_bfloat16* __restrict__ Blo,
    float* __restrict__ C, __nv_bfloat16* __restrict__ Chi, __nv_bfloat16* __restrict__ Clo,
    const float* __restrict__ bias,
    int M, int N, int K,
    long long strA, long long strB, long long strC)
{
    extern __shared__ __align__(1024) char smem[];
    const uint32_t sb = smem_u32(smem);
    const int tid = threadIdx.x, wid = tid >> 5, lane = tid & 31;
    const int row0 = blockIdx.y * 128, col0 = blockIdx.x * 64;

    Ahi += (size_t)blockIdx.z * strA;  Alo += (size_t)blockIdx.z * strA;
    Bhi += (size_t)blockIdx.z * strB;  Blo += (size_t)blockIdx.z * strB;

    // 4m x 2n warp grid, 32x32 warp tiles
    const int wm = wid & 3, wn = wid >> 2;
    const int m0w = wm * 32, n0w = wn * 32;

    // ---- cp.async loader indexing (BK=32 -> 64B rows) ----
    // A tiles: 128 rows x 4 segs; 256 thr -> 2 segs each: row=tid>>1, segs (tid&1)*2+{0,1}
    const int la_row = tid >> 1;
    const int la_s0  = (tid & 1) * 2;
    // B tiles: 64 rows x 4 segs; 1 seg each: row=tid>>2, seg=tid&3
    const int lb_row = tid >> 2;
    const int lb_s   = tid & 3;

    const __nv_bfloat16* gAhi = Ahi + (size_t)(row0 + la_row) * K + la_s0 * 8;
    const __nv_bfloat16* gAlo = Alo + (size_t)(row0 + la_row) * K + la_s0 * 8;
    const __nv_bfloat16* gBhi = Bhi + (size_t)(col0 + lb_row) * K + lb_s * 8;
    const __nv_bfloat16* gBlo = Blo + (size_t)(col0 + lb_row) * K + lb_s * 8;

    // ldmatrix lane addressing (64B rows)
    const uint32_t a_lrow = (uint32_t)(lane & 15);
    const uint32_t a_lc16 = (uint32_t)(lane >> 4) * 16;      // byte offset in row
    const uint32_t b_lrow = (uint32_t)((lane & 7) + ((lane >> 4) & 1) * 8);
    const uint32_t b_lk16 = (uint32_t)((lane >> 3) & 1) * 16;

    float acc[2][4][4];
#pragma unroll
    for (int i = 0; i < 2; i++)
#pragma unroll
        for (int j = 0; j < 4; j++)
#pragma unroll
            for (int q = 0; q < 4; q++) acc[i][j][q] = 0.f;

    const int NCH = K >> 5;   // BK=32

    auto issue = [&](int ch) {
        if (ch < NCH) {
            const uint32_t st = sb + (uint32_t)((ch & 3) * STAGE_B);
            const long long koff = (long long)(ch << 5);
            unsigned long long pah =
                (unsigned long long)__cvta_generic_to_global((const void*)(gAhi + koff));
            unsigned long long pal =
                (unsigned long long)__cvta_generic_to_global((const void*)(gAlo + koff));
            unsigned long long pbh =
                (unsigned long long)__cvta_generic_to_global((const void*)(gBhi + koff));
            unsigned long long pbl =
                (unsigned long long)__cvta_generic_to_global((const void*)(gBlo + koff));
#pragma unroll
            for (int s = 0; s < 2; s++) {
                uint32_t off = (uint32_t)(la_row * 64 + (la_s0 + s) * 16);
                uint32_t sw = sw64(off);
                CP_ASYNC16(st + AH_OFF + sw, pah + s * 16);
                CP_ASYNC16(st + AL_OFF + sw, pal + s * 16);
            }
            {
                uint32_t off = (uint32_t)(lb_row * 64 + lb_s * 16);
                uint32_t sw = sw64(off);
                CP_ASYNC16(st + BH_OFF + sw, pbh);
                CP_ASYNC16(st + BL_OFF + sw, pbl);
            }
        }
        CP_COMMIT();
    };

    // Interleaved phases per k-step: (ldsm Ahi,Bhi -> 8 mma)(ldsm Blo -> 8)(ldsm Alo -> 8)
    auto mma_ks = [&](uint32_t base, int ks) {
        uint32_t aF0[2][4], aF1[2][4], bF0[4][2], bF1[4][2];
#pragma unroll
        for (int mf = 0; mf < 2; mf++) {
            uint32_t off = (uint32_t)((m0w + mf * 16 + a_lrow) * 64 + ks * 32 + a_lc16);
            ldsm_x4(aF0[mf][0], aF0[mf][1], aF0[mf][2], aF0[mf][3],
                    base + AH_OFF + sw64(off));
        }
#pragma unroll
        for (int nfp = 0; nfp < 2; nfp++) {
            uint32_t off = (uint32_t)((n0w + nfp * 16 + b_lrow) * 64 + ks * 32 + b_lk16);
            uint32_t r0, r1, r2, r3;
            ldsm_x4(r0, r1, r2, r3, base + BH_OFF + sw64(off));
            bF0[nfp * 2][0] = r0;      bF0[nfp * 2][1] = r1;
            bF0[nfp * 2 + 1][0] = r2;  bF0[nfp * 2 + 1][1] = r3;
        }
#pragma unroll
        for (int mf = 0; mf < 2; mf++)
#pragma unroll
            for (int nf = 0; nf < 4; nf++) mma16816(acc[mf][nf], aF0[mf], bF0[nf]);
#pragma unroll
        for (int nfp = 0; nfp < 2; nfp++) {
            uint32_t off = (uint32_t)((n0w + nfp * 16 + b_lrow) * 64 + ks * 32 + b_lk16);
            uint32_t r0, r1, r2, r3;
            ldsm_x4(r0, r1, r2, r3, base + BL_OFF + sw64(off));
            bF1[nfp * 2][0] = r0;      bF1[nfp * 2][1] = r1;
            bF1[nfp * 2 + 1][0] = r2;  bF1[nfp * 2 + 1][1] = r3;
        }
#pragma unroll
        for (int mf = 0; mf < 2; mf++)
#pragma unroll
            for (int nf = 0; nf < 4; nf++) mma16816(acc[mf][nf], aF0[mf], bF1[nf]);
#pragma unroll
        for (int mf = 0; mf < 2; mf++) {
            uint32_t off = (uint32_t)((m0w + mf * 16 + a_lrow) * 64 + ks * 32 + a_lc16);
            ldsm_x4(aF1[mf][0], aF1[mf][1], aF1[mf][2], aF1[mf][3],
                    base + AL_OFF + sw64(off));
        }
#pragma unroll
        for (int mf = 0; mf < 2; mf++)
#pragma unroll
            for (int nf = 0; nf < 4; nf++) mma16816(acc[mf][nf], aF1[mf], bF0[nf]);
    };

    // prologue: 3 stages in flight
    issue(0);
    issue(1);
    issue(2);

    for (int ch = 0; ch < NCH; ch++) {
        const uint32_t cur = sb + (uint32_t)((ch & 3) * STAGE_B);
        CP_WAIT2();            // chunk ch resident (<=2 newer groups pending)
        __syncthreads();       // ONE barrier per chunk (ring distance 3 > drift 1)
        issue(ch + 3);         // overlaps with the MMA burst below
        mma_ks(cur, 0);
        mma_ks(cur, 1);
    }
    CP_WAIT0();
    __syncthreads();

    // ---- epilogue: stage accums -> smem [128][68] -> coalesced writes ----
    float* eps = reinterpret_cast<float*>(smem);
    const int g = lane >> 2, c = lane & 3;
#pragma unroll
    for (int mf = 0; mf < 2; mf++)
#pragma unroll
        for (int nf = 0; nf < 4; nf++) {
            int r  = m0w + mf * 16 + g;
            int cc = n0w + nf * 8 + 2 * c;
            *reinterpret_cast<float2*>(&eps[r * 68 + cc]) =
                make_float2(acc[mf][nf][0], acc[mf][nf][1]);
            *reinterpret_cast<float2*>(&eps[(r + 8) * 68 + cc]) =
                make_float2(acc[mf][nf][2], acc[mf][nf][3]);
        }
    __syncthreads();

    if (Chi) {
        __nv_bfloat16* ph = Chi + (size_t)blockIdx.z * strC;
        __nv_bfloat16* pl = Clo + (size_t)blockIdx.z * strC;
#pragma unroll
        for (int it = 0; it < 8; it++) {
            int idx = tid + it * 256;
            int row = idx >> 4;
            int c4  = (idx & 15) << 2;
            float4 v = *reinterpret_cast<float4*>(&eps[row * 68 + c4]);
            float4 bz = *reinterpret_cast<const float4*>(&bias[col0 + c4]);
            v.x += bz.x; v.y += bz.y; v.z += bz.z; v.w += bz.w;
            uint2 hi, lo;
            split2(v, hi, lo);
            size_t o = (size_t)(row0 + row) * N + col0 + c4;
            *reinterpret_cast<uint2*>(&ph[o]) = hi;
            *reinterpret_cast<uint2*>(&pl[o]) = lo;
        }
    } else {
        float* Cb = C + (size_t)blockIdx.z * strC;
#pragma unroll
        for (int it = 0; it < 8; it++) {
            int idx = tid + it * 256;
            int row = idx >> 4;
            int c4  = (idx & 15) << 2;
            float4 v = *reinterpret_cast<float4*>(&eps[row * 68 + c4]);
            *reinterpret_cast<float4*>(&Cb[(size_t)(row0 + row) * N + col0 + c4]) = v;
        }
    }
}

// ============================================================
// prep_x: X -> X_hi/X_lo + XT_hi/XT_lo
// ============================================================
__global__ __launch_bounds__(256) void prep_x(
    const float* __restrict__ X,
    __nv_bfloat16* __restrict__ Xhi, __nv_bfloat16* __restrict__ Xlo,
    __nv_bfloat16* __restrict__ XThi, __nv_bfloat16* __restrict__ XTlo)
{
    __shared__ float t[32][33];
    const int b = blockIdx.z;
    const int s0 = blockIdx.x * 32, d0 = blockIdx.y * 32;
    const size_t bo = (size_t)b * SS * DD;
    const int tx = threadIdx.x, ty = threadIdx.y;
#pragma unroll
    for (int j = 0; j < 4; j++) {
        int s = s0 + ty + 8 * j;
        float v = X[bo + (size_t)s * DD + d0 + tx];
        t[ty + 8 * j][tx] = v;
        __nv_bfloat16 h = __float2bfloat16(v);
        Xhi[bo + (size_t)s * DD + d0 + tx] = h;
        Xlo[bo + (size_t)s * DD + d0 + tx] = __float2bfloat16(v - __bfloat162float(h));
    }
    __syncthreads();
#pragma unroll
    for (int j = 0; j < 4; j++) {
        int d = d0 + ty + 8 * j;
        float v = t[tx][ty + 8 * j];
        __nv_bfloat16 h = __float2bfloat16(v);
        XThi[bo + (size_t)d * SS + s0 + tx] = h;
        XTlo[bo + (size_t)d * SS + s0 + tx] = __float2bfloat16(v - __bfloat162float(h));
    }
}

__global__ __launch_bounds__(256) void split_w(
    const float* __restrict__ W,
    __nv_bfloat16* __restrict__ Whi, __nv_bfloat16* __restrict__ Wlo)
{
    int idx = blockIdx.x * 256 + threadIdx.x;
    float4 v = reinterpret_cast<const float4*>(W)[idx];
    uint2 hi, lo;
    split2(v, hi, lo);
    reinterpret_cast<uint2*>(Whi)[idx] = hi;
    reinterpret_cast<uint2*>(Wlo)[idx] = lo;
}

// ============================================================
// In-place row softmax + split bf16 out
// ============================================================
__device__ __forceinline__ float warp_max(float v) {
#pragma unroll
    for (int o = 16; o > 0; o >>= 1) v = fmaxf(v, __shfl_xor_sync(0xFFFFFFFFu, v, o));
    return v;
}
__device__ __forceinline__ float warp_sum(float v) {
#pragma unroll
    for (int o = 16; o > 0; o >>= 1) v += __shfl_xor_sync(0xFFFFFFFFu, v, o);
    return v;
}

__global__ __launch_bounds__(256) void softmax_rows(
    float* __restrict__ attn,
    __nv_bfloat16* __restrict__ Ahi, __nv_bfloat16* __restrict__ Alo)
{
    __shared__ float red[8];
    const size_t ro = (size_t)blockIdx.x * SS;
    float* row = attn + ro;
    const int tid = threadIdx.x, lane = tid & 31, wid = tid >> 5;

    float4 v[2];
    v[0] = *reinterpret_cast<const float4*>(&row[tid * 4]);
    v[1] = *reinterpret_cast<const float4*>(&row[(tid + 256) * 4]);

    float mx = -INFINITY;
#pragma unroll
    for (int i = 0; i < 2; i++)
        mx = fmaxf(mx, fmaxf(fmaxf(v[i].x, v[i].y), fmaxf(v[i].z, v[i].w)));
    mx = warp_max(mx);
    if (lane == 0) red[wid] = mx;
    __syncthreads();
    if (wid == 0) {
        float t = (lane < 8) ? red[lane] : -INFINITY;
        t = warp_max(t);
        if (lane == 0) red[0] = t;
    }
    __syncthreads();
    mx = red[0];
    __syncthreads();

    float s = 0.f;
#pragma unroll
    for (int i = 0; i < 2; i++) {
        v[i].x = expf(v[i].x - mx); s += v[i].x;
        v[i].y = expf(v[i].y - mx); s += v[i].y;
        v[i].z = expf(v[i].z - mx); s += v[i].z;
        v[i].w = expf(v[i].w - mx); s += v[i].w;
    }
    s = warp_sum(s);
    if (lane == 0) red[wid] = s;
    __syncthreads();
    if (wid == 0) {
        float t = (lane < 8) ? red[lane] : 0.0f;
        t = warp_sum(t);
        if (lane == 0) red[0] = t;
    }
    __syncthreads();
    float inv = 1.0f / red[0];

#pragma unroll
    for (int i = 0; i < 2; i++) { v[i].x *= inv; v[i].y *= inv; v[i].z *= inv; v[i].w *= inv; }
    *reinterpret_cast<float4*>(&row[tid * 4])         = v[0];
    *reinterpret_cast<float4*>(&row[(tid + 256) * 4]) = v[1];

    uint2 hi, lo;
    split2(v[0], hi, lo);
    *reinterpret_cast<uint2*>(&Ahi[ro + tid * 4]) = hi;
    *reinterpret_cast<uint2*>(&Alo[ro + tid * 4]) = lo;
    split2(v[1], hi, lo);
    *reinterpret_cast<uint2*>(&Ahi[ro + (tid + 256) * 4]) = hi;
    *reinterpret_cast<uint2*>(&Alo[ro + (tid + 256) * 4]) = lo;
}

// ============================================================
// kernel_launch
// ============================================================
extern "C" void kernel_launch(void* const* d_in, const int* in_sizes, int n_in,
                              void* d_out, int out_size)
{
    const float* X    = (const float*)d_in[0];
    const float* W    = (const float*)d_in[1];
    const float* bias = (const float*)d_in[2];

    float* ctx  = (float*)d_out;                           // [8,2048,1024]
    float* attn = (float*)d_out + (size_t)BB * SS * DD;    // [8,2048,2048]

    __nv_bfloat16 *xhi, *xlo, *xthi, *xtlo, *whi, *wlo, *phi, *plo, *ahi, *alo;
    cudaGetSymbolAddress((void**)&xhi,  g_xhi);
    cudaGetSymbolAddress((void**)&xlo,  g_xlo);
    cudaGetSymbolAddress((void**)&xthi, g_xthi);
    cudaGetSymbolAddress((void**)&xtlo, g_xtlo);
    cudaGetSymbolAddress((void**)&whi,  g_whi);
    cudaGetSymbolAddress((void**)&wlo,  g_wlo);
    cudaGetSymbolAddress((void**)&phi,  g_phi);
    cudaGetSymbolAddress((void**)&plo,  g_plo);
    cudaGetSymbolAddress((void**)&ahi,  g_ahi);
    cudaGetSymbolAddress((void**)&alo,  g_alo);

    cudaFuncSetAttribute(gemm_nt_mma, cudaFuncAttributeMaxDynamicSharedMemorySize, GEMM_SMEM);

    const long long sXD = (long long)SS * DD;
    const long long sAA = (long long)SS * SS;

    {
        dim3 grid(SS / 32, DD / 32, BB);
        prep_x<<<grid, dim3(32, 8)>>>(X, xhi, xlo, xthi, xtlo);
    }
    split_w<<<(DD * DD / 4) / 256, 256>>>(W, whi, wlo);

    // GEMM1: proj = X * W^T + b  -> split bf16 pair
    {
        dim3 grid(DD / 64, (BB * SS) / 128, 1);
        gemm_nt_mma<<<grid, 256, GEMM_SMEM>>>(xhi, xlo, whi, wlo,
                                              nullptr, phi, plo, bias,
                                              BB * SS, DD, DD, 0, 0, 0);
    }
    // GEMM2: attn[b] = X[b] * proj[b]^T  (fp32 out)
    {
        dim3 grid(SS / 64, SS / 128, BB);
        gemm_nt_mma<<<grid, 256, GEMM_SMEM>>>(xhi, xlo, phi, plo,
                                              attn, nullptr, nullptr, nullptr,
                                              SS, SS, DD, sXD, sXD, sAA);
    }
    softmax_rows<<<BB * SS, 256>>>(attn, ahi, alo);
    // GEMM3: ctx[b] = attn[b] * XT[b]^T  (fp32 out)
    {
        dim3 grid(DD / 64, SS / 128, BB);
        gemm_nt_mma<<<grid, 256, GEMM_SMEM>>>(ahi, alo, xthi, xtlo,
                                              ctx, nullptr, nullptr, nullptr,
                                              SS, DD, SS, sAA, sXD, sXD);
    }
}

// round 9
// speedup vs baseline: 1.5537x; 1.0559x over previous
#include <cuda_runtime.h>
#include <cuda_bf16.h>
#include <math.h>
#include <stdint.h>

// Problem shape (fixed by the dataset)
#define BB 8
#define SS 2048
#define DD 1024

// Pre-split bf16 operand arrays (device globals — allocation-guard-safe)
__device__ __nv_bfloat16 g_xhi[(size_t)BB * SS * DD];
__device__ __nv_bfloat16 g_xlo[(size_t)BB * SS * DD];
__device__ __nv_bfloat16 g_xthi[(size_t)BB * SS * DD];
__device__ __nv_bfloat16 g_xtlo[(size_t)BB * SS * DD];
__device__ __nv_bfloat16 g_whi[(size_t)DD * DD];
__device__ __nv_bfloat16 g_wlo[(size_t)DD * DD];
__device__ __nv_bfloat16 g_phi[(size_t)BB * SS * DD];
__device__ __nv_bfloat16 g_plo[(size_t)BB * SS * DD];
__device__ __nv_bfloat16 g_ahi[(size_t)BB * SS * SS];
__device__ __nv_bfloat16 g_alo[(size_t)BB * SS * SS];

// ============================================================
// R9 GEMM: 256 threads, CTA tile 128(M) x 128(N), BK=16, 4-stage ring,
// ONE __syncthreads per chunk. 8 warps as 2m x 4n, warp tile 64x32
// (2x B-fragment reuse vs R8: 12 LDSM.x4 per 48 MMAs).
// Pre-split bf16 hi/lo operands, 3 products (hh, hl, lh).
// Stage (16KB): Ahi 4K | Alo 4K | Bhi 4K | Blo 4K.  4 stages = 64KB.
// Epilogue reuses smem as float[128][132] (67.6KB total alloc).
// ============================================================

#define AH_OFF 0
#define AL_OFF 4096
#define BH_OFF 8192
#define BL_OFF 12288
#define STAGE_B 16384
#define GEMM_SMEM 67584   // max(4 stages = 64K, epilogue 128*132*4)

__device__ __forceinline__ uint32_t smem_u32(const void* p) {
    uint32_t a;
    asm("{ .reg .u64 t; cvta.to.shared.u64 t, %1; cvt.u32.u64 %0, t; }" : "=r"(a) : "l"(p));
    return a;
}
// Swizzle for 32-byte rows: XOR bit7 (row bit 2) into bit4 (16B seg select).
// Verified conflict-free for 8-lane ldmatrix waves and cp.async stores.
__device__ __forceinline__ uint32_t sw32(uint32_t off) {
    return off ^ ((off >> 3) & 0x10);
}
__device__ __forceinline__ void ldsm_x4(uint32_t& r0, uint32_t& r1, uint32_t& r2, uint32_t& r3,
                                        uint32_t addr) {
    asm volatile("ldmatrix.sync.aligned.m8n8.x4.shared.b16 {%0,%1,%2,%3}, [%4];"
                 : "=r"(r0), "=r"(r1), "=r"(r2), "=r"(r3) : "r"(addr));
}
__device__ __forceinline__ void mma16816(float* d, const uint32_t* a, const uint32_t* b) {
    asm volatile(
        "mma.sync.aligned.m16n8k16.row.col.f32.bf16.bf16.f32 "
        "{%0,%1,%2,%3}, {%4,%5,%6,%7}, {%8,%9}, {%0,%1,%2,%3};"
        : "+f"(d[0]), "+f"(d[1]), "+f"(d[2]), "+f"(d[3])
        : "r"(a[0]), "r"(a[1]), "r"(a[2]), "r"(a[3]), "r"(b[0]), "r"(b[1]));
}

#define CP_ASYNC16(dst, src) \
    asm volatile("cp.async.cg.shared.global [%0], [%1], 16;" :: "r"(dst), "l"(src) : "memory")
#define CP_COMMIT()  asm volatile("cp.async.commit_group;" ::: "memory")
#define CP_WAIT2()   asm volatile("cp.async.wait_group 2;" ::: "memory")
#define CP_WAIT0()   asm volatile("cp.async.wait_group 0;" ::: "memory")

__device__ __forceinline__ void split2(const float4& v, uint2& hi, uint2& lo) {
    __nv_bfloat162 h0 = __floats2bfloat162_rn(v.x, v.y);
    __nv_bfloat162 h1 = __floats2bfloat162_rn(v.z, v.w);
    float r0 = v.x - __bfloat162float(__low2bfloat16(h0));
    float r1 = v.y - __bfloat162float(__high2bfloat16(h0));
    float r2 = v.z - __bfloat162float(__low2bfloat16(h1));
    float r3 = v.w - __bfloat162float(__high2bfloat16(h1));
    __nv_bfloat162 l0 = __floats2bfloat162_rn(r0, r1);
    __nv_bfloat162 l1 = __floats2bfloat162_rn(r2, r3);
    hi.x = *reinterpret_cast<uint32_t*>(&h0);
    hi.y = *reinterpret_cast<uint32_t*>(&h1);
    lo.x = *reinterpret_cast<uint32_t*>(&l0);
    lo.y = *reinterpret_cast<uint32_t*>(&l1);
}

__global__ __launch_bounds__(256, 2) void gemm_nt_mma(
    const __nv_bfloat16* __restrict__ Ahi, const __nv_bfloat16* __restrict__ Alo,
    const __nv_bfloat16* __restrict__ Bhi, const __nv_bfloat16* __restrict__ Blo,
    float* __restrict__ C, __nv_bfloat16* __restrict__ Chi, __nv_bfloat16* __restrict__ Clo,
    const float* __restrict__ bias,
    int M, int N, int K,
    long long strA, long long strB, long long strC)
{
    extern __shared__ __align__(1024) char smem[];
    const uint32_t sb = smem_u32(smem);
    const int tid = threadIdx.x, wid = tid >> 5, lane = tid & 31;
    const int row0 = blockIdx.y * 128, col0 = blockIdx.x * 128;

    Ahi += (size_t)blockIdx.z * strA;  Alo += (size_t)blockIdx.z * strA;
    Bhi += (size_t)blockIdx.z * strB;  Blo += (size_t)blockIdx.z * strB;

    // 2m x 4n warp grid, 64x32 warp tiles
    const int wm = wid & 1, wn = wid >> 1;
    const int m0w = wm * 64, n0w = wn * 32;

    // ---- cp.async loader indexing (BK=16 -> 32B rows, 1 seg/thread/tile) ----
    const int l_row = tid >> 1;       // 0..127
    const int l_s   = tid & 1;        // 16B seg within row

    const __nv_bfloat16* gAhi = Ahi + (size_t)(row0 + l_row) * K + l_s * 8;
    const __nv_bfloat16* gAlo = Alo + (size_t)(row0 + l_row) * K + l_s * 8;
    const __nv_bfloat16* gBhi = Bhi + (size_t)(col0 + l_row) * K + l_s * 8;
    const __nv_bfloat16* gBlo = Blo + (size_t)(col0 + l_row) * K + l_s * 8;

    // ldmatrix lane addressing (32B rows)
    const uint32_t a_lrow = (uint32_t)(lane & 15);
    const uint32_t a_lc16 = (uint32_t)(lane >> 4) * 16;
    const uint32_t b_lrow = (uint32_t)((lane & 7) + ((lane >> 4) & 1) * 8);
    const uint32_t b_lk16 = (uint32_t)((lane >> 3) & 1) * 16;

    float acc[4][4][4];
#pragma unroll
    for (int i = 0; i < 4; i++)
#pragma unroll
        for (int j = 0; j < 4; j++)
#pragma unroll
            for (int q = 0; q < 4; q++) acc[i][j][q] = 0.f;

    const int NCH = K >> 4;   // BK=16

    auto issue = [&](int ch) {
        if (ch < NCH) {
            const uint32_t st = sb + (uint32_t)((ch & 3) * STAGE_B);
            const long long koff = (long long)(ch << 4);
            unsigned long long pah =
                (unsigned long long)__cvta_generic_to_global((const void*)(gAhi + koff));
            unsigned long long pal =
                (unsigned long long)__cvta_generic_to_global((const void*)(gAlo + koff));
            unsigned long long pbh =
                (unsigned long long)__cvta_generic_to_global((const void*)(gBhi + koff));
            unsigned long long pbl =
                (unsigned long long)__cvta_generic_to_global((const void*)(gBlo + koff));
            uint32_t sw = sw32((uint32_t)(l_row * 32 + l_s * 16));
            CP_ASYNC16(st + AH_OFF + sw, pah);
            CP_ASYNC16(st + AL_OFF + sw, pal);
            CP_ASYNC16(st + BH_OFF + sw, pbh);
            CP_ASYNC16(st + BL_OFF + sw, pbl);
        }
        CP_COMMIT();
    };

    // One k-step per chunk: 12 LDSM.x4 -> 48 MMAs in 3 bursts of 16.
    auto mma_ks = [&](uint32_t base) {
        uint32_t aFh[4][4], bFh[4][2], bFl[4][2];
#pragma unroll
        for (int mf = 0; mf < 4; mf++) {
            uint32_t off = (uint32_t)((m0w + mf * 16 + a_lrow) * 32 + a_lc16);
            ldsm_x4(aFh[mf][0], aFh[mf][1], aFh[mf][2], aFh[mf][3],
                    base + AH_OFF + sw32(off));
        }
#pragma unroll
        for (int nfp = 0; nfp < 2; nfp++) {
            uint32_t off = (uint32_t)((n0w + nfp * 16 + b_lrow) * 32 + b_lk16);
            uint32_t r0, r1, r2, r3;
            ldsm_x4(r0, r1, r2, r3, base + BH_OFF + sw32(off));
            bFh[nfp * 2][0] = r0;      bFh[nfp * 2][1] = r1;
            bFh[nfp * 2 + 1][0] = r2;  bFh[nfp * 2 + 1][1] = r3;
        }
#pragma unroll
        for (int nfp = 0; nfp < 2; nfp++) {
            uint32_t off = (uint32_t)((n0w + nfp * 16 + b_lrow) * 32 + b_lk16);
            uint32_t r0, r1, r2, r3;
            ldsm_x4(r0, r1, r2, r3, base + BL_OFF + sw32(off));
            bFl[nfp * 2][0] = r0;      bFl[nfp * 2][1] = r1;
            bFl[nfp * 2 + 1][0] = r2;  bFl[nfp * 2 + 1][1] = r3;
        }
        // burst 1: hh
#pragma unroll
        for (int mf = 0; mf < 4; mf++)
#pragma unroll
            for (int nf = 0; nf < 4; nf++) mma16816(acc[mf][nf], aFh[mf], bFh[nf]);
        // burst 2: h * lo(B)
#pragma unroll
        for (int mf = 0; mf < 4; mf++)
#pragma unroll
            for (int nf = 0; nf < 4; nf++) mma16816(acc[mf][nf], aFh[mf], bFl[nf]);
        // burst 3: lo(A) * h   (aFl loaded late to cap register liveness)
        uint32_t aFl[4][4];
#pragma unroll
        for (int mf = 0; mf < 4; mf++) {
            uint32_t off = (uint32_t)((m0w + mf * 16 + a_lrow) * 32 + a_lc16);
            ldsm_x4(aFl[mf][0], aFl[mf][1], aFl[mf][2], aFl[mf][3],
                    base + AL_OFF + sw32(off));
        }
#pragma unroll
        for (int mf = 0; mf < 4; mf++)
#pragma unroll
            for (int nf = 0; nf < 4; nf++) mma16816(acc[mf][nf], aFl[mf], bFh[nf]);
    };

    // prologue: 3 stages in flight
    issue(0);
    issue(1);
    issue(2);

    for (int ch = 0; ch < NCH; ch++) {
        const uint32_t cur = sb + (uint32_t)((ch & 3) * STAGE_B);
        CP_WAIT2();            // chunk ch resident (<=2 newer groups pending)
        __syncthreads();       // ONE barrier per chunk (ring distance 3 > drift 1)
        issue(ch + 3);         // overlaps with the MMA burst below
        mma_ks(cur);
    }
    CP_WAIT0();
    __syncthreads();

    // ---- epilogue: stage accums -> smem [128][132] -> coalesced writes ----
    float* eps = reinterpret_cast<float*>(smem);
    const int g = lane >> 2, c = lane & 3;
#pragma unroll
    for (int mf = 0; mf < 4; mf++)
#pragma unroll
        for (int nf = 0; nf < 4; nf++) {
            int r  = m0w + mf * 16 + g;
            int cc = n0w + nf * 8 + 2 * c;
            *reinterpret_cast<float2*>(&eps[r * 132 + cc]) =
                make_float2(acc[mf][nf][0], acc[mf][nf][1]);
            *reinterpret_cast<float2*>(&eps[(r + 8) * 132 + cc]) =
                make_float2(acc[mf][nf][2], acc[mf][nf][3]);
        }
    __syncthreads();

    if (Chi) {
        __nv_bfloat16* ph = Chi + (size_t)blockIdx.z * strC;
        __nv_bfloat16* pl = Clo + (size_t)blockIdx.z * strC;
#pragma unroll
        for (int it = 0; it < 16; it++) {
            int idx = tid + it * 256;
            int row = idx >> 5;
            int c4  = (idx & 31) << 2;
            float4 v = *reinterpret_cast<float4*>(&eps[row * 132 + c4]);
            float4 bz = *reinterpret_cast<const float4*>(&bias[col0 + c4]);
            v.x += bz.x; v.y += bz.y; v.z += bz.z; v.w += bz.w;
            uint2 hi, lo;
            split2(v, hi, lo);
            size_t o = (size_t)(row0 + row) * N + col0 + c4;
            *reinterpret_cast<uint2*>(&ph[o]) = hi;
            *reinterpret_cast<uint2*>(&pl[o]) = lo;
        }
    } else {
        float* Cb = C + (size_t)blockIdx.z * strC;
#pragma unroll
        for (int it = 0; it < 16; it++) {
            int idx = tid + it * 256;
            int row = idx >> 5;
            int c4  = (idx & 31) << 2;
            float4 v = *reinterpret_cast<float4*>(&eps[row * 132 + c4]);
            *reinterpret_cast<float4*>(&Cb[(size_t)(row0 + row) * N + col0 + c4]) = v;
        }
    }
}

// ============================================================
// prep_x: X -> X_hi/X_lo + XT_hi/XT_lo
// ============================================================
__global__ __launch_bounds__(256) void prep_x(
    const float* __restrict__ X,
    __nv_bfloat16* __restrict__ Xhi, __nv_bfloat16* __restrict__ Xlo,
    __nv_bfloat16* __restrict__ XThi, __nv_bfloat16* __restrict__ XTlo)
{
    __shared__ float t[32][33];
    const int b = blockIdx.z;
    const int s0 = blockIdx.x * 32, d0 = blockIdx.y * 32;
    const size_t bo = (size_t)b * SS * DD;
    const int tx = threadIdx.x, ty = threadIdx.y;
#pragma unroll
    for (int j = 0; j < 4; j++) {
        int s = s0 + ty + 8 * j;
        float v = X[bo + (size_t)s * DD + d0 + tx];
        t[ty + 8 * j][tx] = v;
        __nv_bfloat16 h = __float2bfloat16(v);
        Xhi[bo + (size_t)s * DD + d0 + tx] = h;
        Xlo[bo + (size_t)s * DD + d0 + tx] = __float2bfloat16(v - __bfloat162float(h));
    }
    __syncthreads();
#pragma unroll
    for (int j = 0; j < 4; j++) {
        int d = d0 + ty + 8 * j;
        float v = t[tx][ty + 8 * j];
        __nv_bfloat16 h = __float2bfloat16(v);
        XThi[bo + (size_t)d * SS + s0 + tx] = h;
        XTlo[bo + (size_t)d * SS + s0 + tx] = __float2bfloat16(v - __bfloat162float(h));
    }
}

__global__ __launch_bounds__(256) void split_w(
    const float* __restrict__ W,
    __nv_bfloat16* __restrict__ Whi, __nv_bfloat16* __restrict__ Wlo)
{
    int idx = blockIdx.x * 256 + threadIdx.x;
    float4 v = reinterpret_cast<const float4*>(W)[idx];
    uint2 hi, lo;
    split2(v, hi, lo);
    reinterpret_cast<uint2*>(Whi)[idx] = hi;
    reinterpret_cast<uint2*>(Wlo)[idx] = lo;
}

// ============================================================
// In-place row softmax + split bf16 out
// ============================================================
__device__ __forceinline__ float warp_max(float v) {
#pragma unroll
    for (int o = 16; o > 0; o >>= 1) v = fmaxf(v, __shfl_xor_sync(0xFFFFFFFFu, v, o));
    return v;
}
__device__ __forceinline__ float warp_sum(float v) {
#pragma unroll
    for (int o = 16; o > 0; o >>= 1) v += __shfl_xor_sync(0xFFFFFFFFu, v, o);
    return v;
}

__global__ __launch_bounds__(256) void softmax_rows(
    float* __restrict__ attn,
    __nv_bfloat16* __restrict__ Ahi, __nv_bfloat16* __restrict__ Alo)
{
    __shared__ float red[8];
    const size_t ro = (size_t)blockIdx.x * SS;
    float* row = attn + ro;
    const int tid = threadIdx.x, lane = tid & 31, wid = tid >> 5;

    float4 v[2];
    v[0] = *reinterpret_cast<const float4*>(&row[tid * 4]);
    v[1] = *reinterpret_cast<const float4*>(&row[(tid + 256) * 4]);

    float mx = -INFINITY;
#pragma unroll
    for (int i = 0; i < 2; i++)
        mx = fmaxf(mx, fmaxf(fmaxf(v[i].x, v[i].y), fmaxf(v[i].z, v[i].w)));
    mx = warp_max(mx);
    if (lane == 0) red[wid] = mx;
    __syncthreads();
    if (wid == 0) {
        float t = (lane < 8) ? red[lane] : -INFINITY;
        t = warp_max(t);
        if (lane == 0) red[0] = t;
    }
    __syncthreads();
    mx = red[0];
    __syncthreads();

    float s = 0.f;
#pragma unroll
    for (int i = 0; i < 2; i++) {
        v[i].x = expf(v[i].x - mx); s += v[i].x;
        v[i].y = expf(v[i].y - mx); s += v[i].y;
        v[i].z = expf(v[i].z - mx); s += v[i].z;
        v[i].w = expf(v[i].w - mx); s += v[i].w;
    }
    s = warp_sum(s);
    if (lane == 0) red[wid] = s;
    __syncthreads();
    if (wid == 0) {
        float t = (lane < 8) ? red[lane] : 0.0f;
        t = warp_sum(t);
        if (lane == 0) red[0] = t;
    }
    __syncthreads();
    float inv = 1.0f / red[0];

#pragma unroll
    for (int i = 0; i < 2; i++) { v[i].x *= inv; v[i].y *= inv; v[i].z *= inv; v[i].w *= inv; }
    *reinterpret_cast<float4*>(&row[tid * 4])         = v[0];
    *reinterpret_cast<float4*>(&row[(tid + 256) * 4]) = v[1];

    uint2 hi, lo;
    split2(v[0], hi, lo);
    *reinterpret_cast<uint2*>(&Ahi[ro + tid * 4]) = hi;
    *reinterpret_cast<uint2*>(&Alo[ro + tid * 4]) = lo;
    split2(v[1], hi, lo);
    *reinterpret_cast<uint2*>(&Ahi[ro + (tid + 256) * 4]) = hi;
    *reinterpret_cast<uint2*>(&Alo[ro + (tid + 256) * 4]) = lo;
}

// ============================================================
// kernel_launch
// ============================================================
extern "C" void kernel_launch(void* const* d_in, const int* in_sizes, int n_in,
                              void* d_out, int out_size)
{
    const float* X    = (const float*)d_in[0];
    const float* W    = (const float*)d_in[1];
    const float* bias = (const float*)d_in[2];

    float* ctx  = (float*)d_out;                           // [8,2048,1024]
    float* attn = (float*)d_out + (size_t)BB * SS * DD;    // [8,2048,2048]

    __nv_bfloat16 *xhi, *xlo, *xthi, *xtlo, *whi, *wlo, *phi, *plo, *ahi, *alo;
    cudaGetSymbolAddress((void**)&xhi,  g_xhi);
    cudaGetSymbolAddress((void**)&xlo,  g_xlo);
    cudaGetSymbolAddress((void**)&xthi, g_xthi);
    cudaGetSymbolAddress((void**)&xtlo, g_xtlo);
    cudaGetSymbolAddress((void**)&whi,  g_whi);
    cudaGetSymbolAddress((void**)&wlo,  g_wlo);
    cudaGetSymbolAddress((void**)&phi,  g_phi);
    cudaGetSymbolAddress((void**)&plo,  g_plo);
    cudaGetSymbolAddress((void**)&ahi,  g_ahi);
    cudaGetSymbolAddress((void**)&alo,  g_alo);

    cudaFuncSetAttribute(gemm_nt_mma, cudaFuncAttributeMaxDynamicSharedMemorySize, GEMM_SMEM);

    const long long sXD = (long long)SS * DD;
    const long long sAA = (long long)SS * SS;

    {
        dim3 grid(SS / 32, DD / 32, BB);
        prep_x<<<grid, dim3(32, 8)>>>(X, xhi, xlo, xthi, xtlo);
    }
    split_w<<<(DD * DD / 4) / 256, 256>>>(W, whi, wlo);

    // GEMM1: proj = X * W^T + b  -> split bf16 pair
    {
        dim3 grid(DD / 128, (BB * SS) / 128, 1);
        gemm_nt_mma<<<grid, 256, GEMM_SMEM>>>(xhi, xlo, whi, wlo,
                                              nullptr, phi, plo, bias,
                                              BB * SS, DD, DD, 0, 0, 0);
    }
    // GEMM2: attn[b] = X[b] * proj[b]^T  (fp32 out)
    {
        dim3 grid(SS / 128, SS / 128, BB);
        gemm_nt_mma<<<grid, 256, GEMM_SMEM>>>(xhi, xlo, phi, plo,
                                              attn, nullptr, nullptr, nullptr,
                                              SS, SS, DD, sXD, sXD, sAA);
    }
    softmax_rows<<<BB * SS, 256>>>(attn, ahi, alo);
    // GEMM3: ctx[b] = attn[b] * XT[b]^T  (fp32 out)
    {
        dim3 grid(DD / 128, SS / 128, BB);
        gemm_nt_mma<<<grid, 256, GEMM_SMEM>>>(ahi, alo, xthi, xtlo,
                                              ctx, nullptr, nullptr, nullptr,
                                              SS, DD, SS, sAA, sXD, sXD);
    }
}